// round 14
// baseline (speedup 1.0000x reference)
#include <cuda_runtime.h>
#include <stdint.h>

#define BB   4
#define NN   1024
#define CC   80
#define KPC  100
#define MAXT 300
#define NEGV (-1e30f)
#define STHR 0.001f
#define CHNK 512     // k_nms chunk capacity (rows in dynamic smem)
#define FSEL 512     // k_final selection cap

// ---------------- scratch ----------------
__device__ uint32_t g_mask[BB * NN * 32];
__device__ float    g_stage_s[BB * CC * KPC];
__device__ int      g_stage_b[BB * CC * KPC];

__device__ __forceinline__ uint32_t dbits(float f) {
    uint32_t u = __float_as_uint(f);
    return (u & 0x80000000u) ? u : (u ^ 0x7fffffffu);
}
__device__ __forceinline__ float undbits_pos(uint32_t d) {
    return __uint_as_float(d ^ 0x7fffffffu);   // valid for positive originals
}

// ---------------- K1: pairwise IoU>0.5 bitmask (2 rows/thread, 16-bit stores) ----------------
// grid (256, BB) x 128 threads. Block = 16 rows x 256 cols; thread = 2 rows x 16 cols.
// Exact decision vs rn(inter/uni)>0.5:  2*inter - uni > uni*2^-24.
__global__ void __launch_bounds__(128) k_mask(const float4* __restrict__ boxes) {
    __shared__ float4 sj[256]; __shared__ float aj[256];
    __shared__ float4 si[16];  __shared__ float ai[16];
    const int b  = blockIdx.y;
    const int rt = blockIdx.x >> 2;    // 64 row tiles of 16 rows
    const int ct = blockIdx.x & 3;     // 4 col tiles of 256 cols
    const int tid = threadIdx.x;

    #pragma unroll
    for (int k = 0; k < 2; k++) {
        int i = tid + k * 128;
        float4 v = boxes[b * NN + ct * 256 + i];
        float y1 = fminf(v.x, v.z), y2 = fmaxf(v.x, v.z);
        float x1 = fminf(v.y, v.w), x2 = fmaxf(v.y, v.w);
        sj[i] = make_float4(y1, x1, y2, x2);
        aj[i] = (y2 - y1) * (x2 - x1);
    }
    if (tid < 16) {
        float4 v = boxes[b * NN + rt * 16 + tid];
        float y1 = fminf(v.x, v.z), y2 = fmaxf(v.x, v.z);
        float x1 = fminf(v.y, v.w), x2 = fmaxf(v.y, v.w);
        si[tid] = make_float4(y1, x1, y2, x2);
        ai[tid] = (y2 - y1) * (x2 - x1);
    }
    __syncthreads();

    const int r    = tid >> 4;     // 0..7 -> rows r and r+8
    const int hw   = tid & 15;     // halfword (16 columns)
    const int lane = tid & 31;
    float4 A0 = si[r],     A1 = si[r + 8];
    float  a0 = ai[r],     a1 = ai[r + 8];
    uint32_t bits0 = 0, bits1 = 0;

    #pragma unroll
    for (int t = 0; t < 16; t++) {
        int c  = (t + lane) & 15;
        int jl = hw * 16 + c;
        float4 Bx = sj[jl];
        float  ab = aj[jl];
        {
            float ih    = fmaxf(fminf(A0.z, Bx.z) - fmaxf(A0.x, Bx.x), 0.0f);
            float iw2   = fmaxf(fminf(A0.w, Bx.w) - fmaxf(A0.y, Bx.y), 0.0f);
            float inter = ih * iw2;
            float uni   = fmaxf(a0 + ab - inter, 1e-12f);
            if ((inter + inter) - uni > uni * 0x1p-24f) bits0 |= (1u << c);
        }
        {
            float ih    = fmaxf(fminf(A1.z, Bx.z) - fmaxf(A1.x, Bx.x), 0.0f);
            float iw2   = fmaxf(fminf(A1.w, Bx.w) - fmaxf(A1.y, Bx.y), 0.0f);
            float inter = ih * iw2;
            float uni   = fmaxf(a1 + ab - inter, 1e-12f);
            if ((inter + inter) - uni > uni * 0x1p-24f) bits1 |= (1u << c);
        }
    }
    uint16_t* gm16 = reinterpret_cast<uint16_t*>(g_mask);
    gm16[(size_t)(b * NN + rt * 16 + r)     * 64 + ct * 16 + hw] = (uint16_t)bits0;
    gm16[(size_t)(b * NN + rt * 16 + r + 8) * 64 + ct * 16 + hw] = (uint16_t)bits1;
}

// ---------------- K2: 512-chunk bucket-select + alive filter + tiered sort + ballot greedy ----------------
__global__ void __launch_bounds__(256) k_nms(const float* __restrict__ scores) {
    extern __shared__ __align__(16) uint32_t rows[];   // 64KB dynamic: CHNK*32 u32
    __shared__ uint32_t hist[1025];
    __shared__ uint32_t chkey[CHNK];
    __shared__ uint16_t chidx[CHNK];
    __shared__ uint32_t sup_sh[32];
    __shared__ float    kept_s[KPC];
    __shared__ int      kept_i[KPC];
    __shared__ uint32_t wsum[8];
    __shared__ int      s_cnt, s_bhi, s_kc, s_done, s_fb;

    const int c    = blockIdx.x;
    const int b    = blockIdx.y;
    const int tid  = threadIdx.x;
    const int lane = tid & 31;
    const uint32_t BASE = 0x80F;             // dbits(1.0f) >> 19

    #pragma unroll
    for (int k = 0; k < 4; k++) hist[tid * 4 + k] = 0;
    if (tid < 32) sup_sh[tid] = 0;
    if (tid == 0) { hist[1024] = 0; s_kc = 0; s_done = 0; s_fb = 0; }

    uint32_t key[4], binv[4]; bool val[4];
    #pragma unroll
    for (int k = 0; k < 4; k++) {
        int i = tid + k * 256;
        float s = scores[(b * NN + i) * CC + c];
        val[k] = (s > STHR);
        key[k] = dbits(s);
        int raw = (int)(key[k] >> 19) - (int)BASE;
        binv[k] = (uint32_t)min(max(raw, 0), 1023);
    }
    __syncthreads();
    #pragma unroll
    for (int k = 0; k < 4; k++) if (val[k]) atomicAdd(&hist[binv[k]], 1u);
    __syncthreads();

    // exclusive scan of 1024 bins (4 bins/thread, 8 warps)
    {
        uint32_t h[4];
        #pragma unroll
        for (int k = 0; k < 4; k++) h[k] = hist[4 * tid + k];
        uint32_t s4 = h[0] + h[1] + h[2] + h[3];
        uint32_t inc = s4;
        #pragma unroll
        for (int o = 1; o < 32; o <<= 1) {
            uint32_t v = __shfl_up_sync(0xffffffffu, inc, o);
            if ((tid & 31) >= o) inc += v;
        }
        if ((tid & 31) == 31) wsum[tid >> 5] = inc;
        __syncthreads();
        if (tid < 8) {
            uint32_t v = wsum[tid], in2 = v;
            #pragma unroll
            for (int o = 1; o < 8; o <<= 1) {
                uint32_t x = __shfl_up_sync(0x000000ffu, in2, o);
                if (tid >= o) in2 += x;
            }
            wsum[tid] = in2 - v;
        }
        __syncthreads();
        uint32_t excl = wsum[tid >> 5] + (inc - s4);
        uint32_t c1 = excl + h[0], c2 = c1 + h[1], c3 = c2 + h[2], c4 = excl + s4;
        hist[4 * tid] = excl; hist[4 * tid + 1] = c1; hist[4 * tid + 2] = c2; hist[4 * tid + 3] = c3;
        if (tid == 255) hist[1024] = c4;
    }
    __syncthreads();

    const int total = (int)hist[1024];
    uint32_t sup = 0;    // persistent suppressed bitmap (warp0, lane w = word w)
    int      kc  = 0;    // persistent kept count (warp0)
    int binLo = 0;

    for (int chunk = 0; chunk < 8; chunk++) {
        if (s_kc >= KPC || s_done >= total) break;

        if (tid == 0) { s_bhi = binLo; s_cnt = 0; }
        __syncthreads();
        const uint32_t base = hist[binLo];
        #pragma unroll
        for (int k = 1; k <= 4; k++) {
            int e = 4 * tid + k;
            if (hist[e] - base <= (uint32_t)CHNK) atomicMax(&s_bhi, e);
        }
        __syncthreads();
        const int binHi = s_bhi;
        if (binHi == binLo) { if (tid == 0) s_fb = 1; __syncthreads(); break; }
        const int rangeCnt = (int)(hist[binHi] - base);   // unfiltered examined count

        // compact chunk members, dropping already-suppressed candidates (exact: monotone)
        #pragma unroll
        for (int k = 0; k < 4; k++) {
            int i = tid + k * 256;
            if (val[k] && binv[k] >= (uint32_t)binLo && binv[k] < (uint32_t)binHi &&
                !((sup_sh[i >> 5] >> (i & 31)) & 1u)) {
                int pos = atomicAdd(&s_cnt, 1);
                chkey[pos] = key[k];
                chidx[pos] = (uint16_t)i;
            }
        }
        __syncthreads();
        const int P = s_cnt;
        if (tid >= P)       { chkey[tid] = 0xFFFFFFFFu;       chidx[tid] = 0xFFFF; }
        if (tid + 256 >= P) { chkey[tid + 256] = 0xFFFFFFFFu; chidx[tid + 256] = 0xFFFF; }
        __syncthreads();

        if (P > 0) {
            if (P <= 32) {
                // tiny chunk: pure-shfl 32-element warp bitonic on warp 0
                if (tid < 32) {
                    uint32_t mk = chkey[tid], mi = chidx[tid];
                    for (int k2 = 2; k2 <= 32; k2 <<= 1) {
                        for (int j = k2 >> 1; j > 0; j >>= 1) {
                            uint32_t pk = __shfl_xor_sync(0xffffffffu, mk, j);
                            uint32_t pi = __shfl_xor_sync(0xffffffffu, mi, j);
                            bool up = ((tid & k2) == 0);
                            bool keep_min = (((tid & j) == 0) == up);
                            bool plt = (pk < mk) || (pk == mk && pi < mi);
                            if (keep_min == plt) { mk = pk; mi = pi; }
                        }
                    }
                    chkey[tid] = mk; chidx[tid] = (uint16_t)mi;
                }
                __syncthreads();
            } else if (P <= 256) {
                // medium chunk: 256-element hybrid (1 elem/thread)
                uint32_t mk = chkey[tid], mi = chidx[tid];
                for (int k2 = 2; k2 <= 256; k2 <<= 1) {
                    for (int j = k2 >> 1; j > 0; j >>= 1) {
                        if (j >= 32) {
                            __syncthreads();
                            chkey[tid] = mk; chidx[tid] = (uint16_t)mi;
                            __syncthreads();
                            int p2 = tid ^ j;
                            uint32_t pk = chkey[p2], pi = chidx[p2];
                            bool up = ((tid & k2) == 0);
                            bool keep_min = (((tid & j) == 0) == up);
                            bool plt = (pk < mk) || (pk == mk && pi < mi);
                            if (keep_min == plt) { mk = pk; mi = pi; }
                        } else {
                            uint32_t pk = __shfl_xor_sync(0xffffffffu, mk, j);
                            uint32_t pi = __shfl_xor_sync(0xffffffffu, mi, j);
                            bool up = ((tid & k2) == 0);
                            bool keep_min = (((tid & j) == 0) == up);
                            bool plt = (pk < mk) || (pk == mk && pi < mi);
                            if (keep_min == plt) { mk = pk; mi = pi; }
                        }
                    }
                }
                __syncthreads();
                chkey[tid] = mk; chidx[tid] = (uint16_t)mi;
                __syncthreads();
            } else {
                // large chunk: 512-element hybrid, 2 elems/thread (tid, tid+256)
                uint32_t k0 = chkey[tid],       i0 = chidx[tid];
                uint32_t k1 = chkey[tid + 256], i1 = chidx[tid + 256];
                for (int k2 = 2; k2 <= 512; k2 <<= 1) {
                    for (int j = k2 >> 1; j > 0; j >>= 1) {
                        if (j >= 32) {
                            chkey[tid] = k0; chidx[tid] = (uint16_t)i0;
                            chkey[tid + 256] = k1; chidx[tid + 256] = (uint16_t)i1;
                            __syncthreads();
                            int e = ((tid & ~(j - 1)) << 1) | (tid & (j - 1));
                            int p = e | j;
                            bool up = ((e & k2) == 0);
                            uint32_t ka = chkey[e], kb = chkey[p];
                            uint32_t ia = chidx[e], ib = chidx[p];
                            bool agb = (ka > kb) || (ka == kb && ia > ib);
                            if (agb == up) {
                                chkey[e] = kb; chkey[p] = ka;
                                chidx[e] = (uint16_t)ib; chidx[p] = (uint16_t)ia;
                            }
                            __syncthreads();
                            k0 = chkey[tid];       i0 = chidx[tid];
                            k1 = chkey[tid + 256]; i1 = chidx[tid + 256];
                        } else {
                            {
                                uint32_t pk = __shfl_xor_sync(0xffffffffu, k0, j);
                                uint32_t pi = __shfl_xor_sync(0xffffffffu, i0, j);
                                bool up = ((tid & k2) == 0);
                                bool keep_min = (((tid & j) == 0) == up);
                                bool plt = (pk < k0) || (pk == k0 && pi < i0);
                                if (keep_min == plt) { k0 = pk; i0 = pi; }
                            }
                            {
                                uint32_t pk = __shfl_xor_sync(0xffffffffu, k1, j);
                                uint32_t pi = __shfl_xor_sync(0xffffffffu, i1, j);
                                bool up = (((tid + 256) & k2) == 0);
                                bool keep_min = (((tid & j) == 0) == up);
                                bool plt = (pk < k1) || (pk == k1 && pi < i1);
                                if (keep_min == plt) { k1 = pk; i1 = pi; }
                            }
                        }
                    }
                }
                chkey[tid] = k0; chidx[tid] = (uint16_t)i0;
                chkey[tid + 256] = k1; chidx[tid + 256] = (uint16_t)i1;
                __syncthreads();
            }

            // preload chunk mask rows (vectorized, alive candidates only)
            {
                const uint4* gm4 = reinterpret_cast<const uint4*>(g_mask);
                uint4* rw4 = reinterpret_cast<uint4*>(rows);
                for (int l = tid; l < P * 8; l += 256) {
                    int r = l >> 3, q = l & 7;
                    int o = (int)chidx[r];
                    rw4[(r << 3) | q] = gm4[(b * NN + o) * 8 + q];
                }
            }
            __syncthreads();

            // group-of-32 parallel greedy on warp 0
            if (tid < 32) {
                const uint32_t lowmask = (lane == 0) ? 0u : (0xffffffffu >> (32 - lane));
                for (int g0 = 0; g0 < P && kc < KPC; g0 += 32) {
                    int l = g0 + lane;
                    bool has = (l < P);
                    uint32_t o = 0, keyv = 0xFFFFFFFFu;
                    if (has) { o = chidx[l]; keyv = chkey[l]; }
                    uint32_t wl2 = o >> 5, bl = o & 31;

                    uint32_t wsup = __shfl_sync(0xffffffffu, sup, (int)wl2);
                    bool alive0 = has && !((wsup >> bl) & 1u);
                    uint32_t alive_mask = __ballot_sync(0xffffffffu, alive0);
                    if (alive_mask == 0) continue;     // whole group already suppressed

                    uint32_t colbits = 0;
                    int gcnt = min(32, P - g0);
                    for (int m = 0; m < gcnt; m++) {
                        uint32_t rm = rows[((g0 + m) << 5) + wl2];
                        colbits |= ((rm >> bl) & 1u) << m;
                    }

                    #pragma unroll 4
                    for (int it = 0; it < 32; it++) {
                        bool a = alive0 && ((alive_mask & colbits & lowmask) == 0);
                        uint32_t nm = __ballot_sync(0xffffffffu, a);
                        if (nm == alive_mask) break;
                        alive_mask = nm;
                    }

                    int navail = KPC - kc;
                    int myrank = __popc(alive_mask & lowmask);
                    bool keepme = ((alive_mask >> lane) & 1u) && (myrank < navail);
                    uint32_t kept_mask = __ballot_sync(0xffffffffu, keepme);
                    if (keepme) {
                        kept_i[kc + myrank] = (int)o;
                        kept_s[kc + myrank] = undbits_pos(keyv);
                    }
                    uint32_t km = kept_mask;
                    while (km) {
                        int m = __ffs(km) - 1; km &= km - 1;
                        sup |= rows[((g0 + m) << 5) + lane];
                    }
                    kc += __popc(kept_mask);
                }
                sup_sh[lane] = sup;                    // publish for next chunk's filter
                if (lane == 0) s_kc = kc;
            }
        }
        __syncthreads();
        if (tid == 0) s_done += rangeCnt;
        binLo = binHi;
        __syncthreads();
    }
    __syncthreads();

    // fallback: degenerate distribution (never expected) -> full sort + sequential greedy
    if (s_fb || (s_kc < KPC && s_done < total)) {
        uint64_t* keys = reinterpret_cast<uint64_t*>(rows);
        #pragma unroll
        for (int k = 0; k < 4; k++) {
            int i = tid + k * 256;
            uint32_t kb = val[k] ? key[k] : 0xFFFFFFFFu;
            keys[i] = (((uint64_t)kb) << 32) | (uint32_t)i;
        }
        __syncthreads();
        for (int k2 = 2; k2 <= NN; k2 <<= 1) {
            for (int j = k2 >> 1; j > 0; j >>= 1) {
                #pragma unroll
                for (int t2 = 0; t2 < 4; t2++) {
                    int i2 = tid + t2 * 256, ixj = i2 ^ j;
                    if (ixj > i2) {
                        uint64_t a = keys[i2], d2 = keys[ixj];
                        bool up = ((i2 & k2) == 0);
                        if ((a > d2) == up) { keys[i2] = d2; keys[ixj] = a; }
                    }
                }
                __syncthreads();
            }
        }
        if (tid < 32) {
            uint32_t sup2 = 0; int kc2 = 0;
            for (int p = 0; p < NN; p++) {
                uint64_t kk = keys[p];
                if ((uint32_t)(kk >> 32) == 0xFFFFFFFFu) break;
                uint32_t o   = (uint32_t)kk & (NN - 1);
                uint32_t row = g_mask[(b * NN + o) * 32 + tid];
                uint32_t wv  = __shfl_sync(0xffffffffu, sup2, (int)(o >> 5));
                if (!((wv >> (o & 31)) & 1u)) {
                    if (tid == 0) { kept_i[kc2] = (int)o; kept_s[kc2] = undbits_pos((uint32_t)(kk >> 32)); }
                    sup2 |= row;
                    kc2++;
                    if (kc2 == KPC) break;
                }
            }
            if (tid == 0) s_kc = kc2;
        }
        __syncthreads();
    }

    const int kcf = s_kc;
    if (tid < KPC) {
        int slot = (b * CC + c) * KPC + tid;
        if (tid < kcf) { g_stage_s[slot] = kept_s[tid]; g_stage_b[slot] = kept_i[tid]; }
        else           { g_stage_s[slot] = NEGV;        g_stage_b[slot] = 0; }
    }
}

// ---------------- K3: per-image top-300 of 8000 + output (R10 proven version) ----------------
__global__ void __launch_bounds__(1024) k_final(const float* __restrict__ boxes,
                                                float* __restrict__ out) {
    __shared__ uint32_t hist[4097];
    __shared__ uint32_t fkey[FSEL];
    __shared__ uint16_t fidx[FSEL];
    __shared__ uint32_t wsum[32];
    __shared__ int      s_cnt, s_bsel, s_total, s_m;

    const int b   = blockIdx.x;
    const int tid = threadIdx.x;
    const int M   = CC * KPC;
    const uint32_t BASE13 = 0x203FF;         // dbits(1.0f) >> 13

    #pragma unroll
    for (int k = 0; k < 4; k++) hist[tid * 4 + k] = 0;
    if (tid == 0) { hist[4096] = 0; s_cnt = 0; s_bsel = 0; }

    float vals[8]; int idxs[8]; uint32_t keyb[8]; uint32_t binb[8]; bool valb[8];
    #pragma unroll
    for (int k = 0; k < 8; k++) {
        int f = tid + k * 1024;
        float s = (f < M) ? g_stage_s[b * M + f] : NEGV;
        vals[k] = s; idxs[k] = (f < M) ? f : 0;
        valb[k] = (s > NEGV * 0.5f);
        keyb[k] = dbits(s);
        int raw = (int)(keyb[k] >> 13) - (int)BASE13;
        binb[k] = (uint32_t)min(max(raw, 0), 4095);
    }
    __syncthreads();
    #pragma unroll
    for (int k = 0; k < 8; k++) if (valb[k]) atomicAdd(&hist[binb[k]], 1u);
    __syncthreads();

    uint32_t h[4];
    #pragma unroll
    for (int k = 0; k < 4; k++) h[k] = hist[4 * tid + k];
    uint32_t s4 = h[0] + h[1] + h[2] + h[3];
    uint32_t inc = s4;
    #pragma unroll
    for (int o = 1; o < 32; o <<= 1) {
        uint32_t v = __shfl_up_sync(0xffffffffu, inc, o);
        if ((tid & 31) >= o) inc += v;
    }
    if ((tid & 31) == 31) wsum[tid >> 5] = inc;
    __syncthreads();
    if (tid < 32) {
        uint32_t v = wsum[tid], in2 = v;
        #pragma unroll
        for (int o = 1; o < 32; o <<= 1) {
            uint32_t x = __shfl_up_sync(0xffffffffu, in2, o);
            if (tid >= o) in2 += x;
        }
        wsum[tid] = in2 - v;
    }
    __syncthreads();
    uint32_t excl = wsum[tid >> 5] + (inc - s4);
    uint32_t cum1 = excl + h[0], cum2 = cum1 + h[1], cum3 = cum2 + h[2], cum4 = excl + s4;
    hist[4 * tid] = excl; hist[4 * tid + 1] = cum1; hist[4 * tid + 2] = cum2; hist[4 * tid + 3] = cum3;
    if (tid == 1023) hist[4096] = cum4;
    if (cum1 <= (uint32_t)FSEL) atomicMax(&s_bsel, 4 * tid + 1);
    if (cum2 <= (uint32_t)FSEL) atomicMax(&s_bsel, 4 * tid + 2);
    if (cum3 <= (uint32_t)FSEL) atomicMax(&s_bsel, 4 * tid + 3);
    if (cum4 <= (uint32_t)FSEL) atomicMax(&s_bsel, 4 * tid + 4);
    __syncthreads();

    const int Bsel  = s_bsel;
    int P           = (int)hist[Bsel];
    const int total = (int)hist[4096];

    if (P >= MAXT || P >= total) {
        #pragma unroll
        for (int k = 0; k < 8; k++) {
            if (valb[k] && binb[k] < (uint32_t)Bsel) {
                int pos = atomicAdd(&s_cnt, 1);
                if (pos < FSEL) { fkey[pos] = keyb[k]; fidx[pos] = (uint16_t)idxs[k]; }
            }
        }
        if (tid == 0) s_m = P;
    } else {
        float lo = 0.0f, hi2 = 1.0f;
        for (int it = 0; it < 30; it++) {
            float mid = 0.5f * (lo + hi2);
            int cnt = 0;
            #pragma unroll
            for (int k = 0; k < 8; k++) cnt += (vals[k] > mid);
            #pragma unroll
            for (int o = 16; o; o >>= 1) cnt += __shfl_down_sync(0xffffffffu, cnt, o);
            if ((tid & 31) == 0) wsum[tid >> 5] = (uint32_t)cnt;
            __syncthreads();
            if (tid == 0) {
                int tot = 0;
                #pragma unroll
                for (int w2 = 0; w2 < 32; w2++) tot += (int)wsum[w2];
                s_total = tot;
            }
            __syncthreads();
            if (s_total >= MAXT) lo = mid; else hi2 = mid;
            __syncthreads();
        }
        if (tid == 0) s_cnt = 0;
        __syncthreads();
        #pragma unroll
        for (int k = 0; k < 8; k++) {
            if (vals[k] > lo) {
                int pos = atomicAdd(&s_cnt, 1);
                if (pos < FSEL) { fkey[pos] = dbits(vals[k]); fidx[pos] = (uint16_t)idxs[k]; }
            }
        }
        __syncthreads();
        if (tid == 0) s_m = min(s_cnt, FSEL);
    }
    __syncthreads();
    const int m = s_m;
    if (tid < FSEL && tid >= m) { fkey[tid] = 0xFFFFFFFFu; fidx[tid] = 0xFFFF; }
    __syncthreads();

    // hybrid bitonic sort FSEL: (key,idx) ascending; intra-warp via shfl
    {
        uint32_t mk = 0xFFFFFFFFu, mi = 0xFFFFu;
        if (tid < FSEL) { mk = fkey[tid]; mi = fidx[tid]; }
        for (int k2 = 2; k2 <= FSEL; k2 <<= 1) {
            for (int j = k2 >> 1; j > 0; j >>= 1) {
                if (j >= 32) {
                    __syncthreads();
                    if (tid < FSEL) { fkey[tid] = mk; fidx[tid] = (uint16_t)mi; }
                    __syncthreads();
                    if (tid < FSEL) {
                        int p2 = tid ^ j;
                        uint32_t pk = fkey[p2], pi = fidx[p2];
                        bool up = ((tid & k2) == 0);
                        bool keep_min = (((tid & j) == 0) == up);
                        bool plt = (pk < mk) || (pk == mk && pi < mi);
                        if (keep_min == plt) { mk = pk; mi = pi; }
                    }
                } else if (tid < FSEL) {
                    uint32_t pk = __shfl_xor_sync(0xffffffffu, mk, j);
                    uint32_t pi = __shfl_xor_sync(0xffffffffu, mi, j);
                    bool up = ((tid & k2) == 0);
                    bool keep_min = (((tid & j) == 0) == up);
                    bool plt = (pk < mk) || (pk == mk && pi < mi);
                    if (keep_min == plt) { mk = pk; mi = pi; }
                }
            }
        }
        __syncthreads();
        if (tid < FSEL) { fkey[tid] = mk; fidx[tid] = (uint16_t)mi; }
        __syncthreads();
    }

    if (tid < MAXT) {
        bool valid = (tid < m);
        float sc = 0.0f, cls = 0.0f, bx0 = 0.0f, bx1 = 0.0f, bx2 = 0.0f, bx3 = 0.0f;
        if (valid) {
            int f = (int)fidx[tid];
            sc  = g_stage_s[b * M + f];
            cls = (float)(f / KPC);
            int bidx = g_stage_b[b * M + f];
            float4 bv = reinterpret_cast<const float4*>(boxes)[b * NN + bidx];
            bx0 = fminf(fmaxf(bv.x, 0.0f), 1.0f);
            bx1 = fminf(fmaxf(bv.y, 0.0f), 1.0f);
            bx2 = fminf(fmaxf(bv.z, 0.0f), 1.0f);
            bx3 = fminf(fmaxf(bv.w, 0.0f), 1.0f);
        }
        out[b * MAXT + tid] = sc;
        float* ob = out + BB * MAXT + (b * MAXT + tid) * 4;
        ob[0] = bx0; ob[1] = bx1; ob[2] = bx2; ob[3] = bx3;
        out[BB * MAXT * 5 + b * MAXT + tid] = cls;
    }
    if (tid == 0) out[BB * MAXT * 6 + b] = (float)min(m, MAXT);
}

// ---------------- launch ----------------
extern "C" void kernel_launch(void* const* d_in, const int* in_sizes, int n_in,
                              void* d_out, int out_size) {
    const float* scores = (const float*)d_in[0];   // [4,1024,80] f32
    const float* boxes  = (const float*)d_in[1];   // [4,1024,1,4] f32
    float* out = (float*)d_out;

    const int nms_smem = CHNK * 32 * (int)sizeof(uint32_t);   // 64KB dynamic
    cudaFuncSetAttribute(k_nms, cudaFuncAttributeMaxDynamicSharedMemorySize, nms_smem);

    k_mask<<<dim3(256, BB), 128>>>((const float4*)boxes);
    k_nms<<<dim3(CC, BB), 256, nms_smem>>>(scores);
    k_final<<<BB, 1024>>>(boxes, out);
}

// round 15
// speedup vs baseline: 1.1727x; 1.1727x over previous
#include <cuda_runtime.h>
#include <stdint.h>

#define BB   4
#define NN   1024
#define CC   80
#define KPC  100
#define MAXT 300
#define NEGV (-1e30f)
#define STHR 0.001f
#define CHNK 256     // k_nms chunk capacity
#define FSEL 512     // k_final selection cap

// ---------------- scratch ----------------
__device__ uint32_t g_mask[BB * NN * 32];
__device__ float    g_scoresT[BB * CC * NN];    // transposed scores [B,C,N]
__device__ float    g_stage_s[BB * CC * KPC];
__device__ int      g_stage_b[BB * CC * KPC];

__device__ __forceinline__ uint32_t dbits(float f) {
    uint32_t u = __float_as_uint(f);
    return (u & 0x80000000u) ? u : (u ^ 0x7fffffffu);
}
__device__ __forceinline__ float undbits_pos(uint32_t d) {
    return __uint_as_float(d ^ 0x7fffffffu);   // valid for positive originals
}

// ---------------- K0: transpose scores [B,N,C] -> [B,C,N] (coalesced both sides) ----------------
__global__ void __launch_bounds__(256) k_tr(const float* __restrict__ scores) {
    __shared__ float tile[32 * 81];            // 81 pad -> conflict-free column reads
    const int b  = blockIdx.y;
    const int n0 = blockIdx.x * 32;
    const int base = (b * NN + n0) * CC;
    for (int idx = threadIdx.x; idx < 32 * CC; idx += 256) {
        int nn = idx / CC, cc = idx % CC;
        tile[nn * 81 + cc] = scores[base + idx];
    }
    __syncthreads();
    for (int odx = threadIdx.x; odx < CC * 32; odx += 256) {
        int cc = odx >> 5, nn = odx & 31;
        g_scoresT[(b * CC + cc) * NN + n0 + nn] = tile[nn * 81 + cc];
    }
}

// ---------------- K1: pairwise IoU>0.5 bitmask (2 rows/thread, 16-bit stores) ----------------
__global__ void __launch_bounds__(128) k_mask(const float4* __restrict__ boxes) {
    __shared__ float4 sj[256]; __shared__ float aj[256];
    __shared__ float4 si[16];  __shared__ float ai[16];
    const int b  = blockIdx.y;
    const int rt = blockIdx.x >> 2;
    const int ct = blockIdx.x & 3;
    const int tid = threadIdx.x;

    #pragma unroll
    for (int k = 0; k < 2; k++) {
        int i = tid + k * 128;
        float4 v = boxes[b * NN + ct * 256 + i];
        float y1 = fminf(v.x, v.z), y2 = fmaxf(v.x, v.z);
        float x1 = fminf(v.y, v.w), x2 = fmaxf(v.y, v.w);
        sj[i] = make_float4(y1, x1, y2, x2);
        aj[i] = (y2 - y1) * (x2 - x1);
    }
    if (tid < 16) {
        float4 v = boxes[b * NN + rt * 16 + tid];
        float y1 = fminf(v.x, v.z), y2 = fmaxf(v.x, v.z);
        float x1 = fminf(v.y, v.w), x2 = fmaxf(v.y, v.w);
        si[tid] = make_float4(y1, x1, y2, x2);
        ai[tid] = (y2 - y1) * (x2 - x1);
    }
    __syncthreads();

    const int r    = tid >> 4;
    const int hw   = tid & 15;
    const int lane = tid & 31;
    float4 A0 = si[r],     A1 = si[r + 8];
    float  a0 = ai[r],     a1 = ai[r + 8];
    uint32_t bits0 = 0, bits1 = 0;

    #pragma unroll
    for (int t = 0; t < 16; t++) {
        int c  = (t + lane) & 15;
        int jl = hw * 16 + c;
        float4 Bx = sj[jl];
        float  ab = aj[jl];
        {
            float ih    = fmaxf(fminf(A0.z, Bx.z) - fmaxf(A0.x, Bx.x), 0.0f);
            float iw2   = fmaxf(fminf(A0.w, Bx.w) - fmaxf(A0.y, Bx.y), 0.0f);
            float inter = ih * iw2;
            float uni   = fmaxf(a0 + ab - inter, 1e-12f);
            if ((inter + inter) - uni > uni * 0x1p-24f) bits0 |= (1u << c);
        }
        {
            float ih    = fmaxf(fminf(A1.z, Bx.z) - fmaxf(A1.x, Bx.x), 0.0f);
            float iw2   = fmaxf(fminf(A1.w, Bx.w) - fmaxf(A1.y, Bx.y), 0.0f);
            float inter = ih * iw2;
            float uni   = fmaxf(a1 + ab - inter, 1e-12f);
            if ((inter + inter) - uni > uni * 0x1p-24f) bits1 |= (1u << c);
        }
    }
    uint16_t* gm16 = reinterpret_cast<uint16_t*>(g_mask);
    gm16[(size_t)(b * NN + rt * 16 + r)     * 64 + ct * 16 + hw] = (uint16_t)bits0;
    gm16[(size_t)(b * NN + rt * 16 + r + 8) * 64 + ct * 16 + hw] = (uint16_t)bits1;
}

// ---------------- K2: chunked bucket-select + alive filter + tiered sort + ballot greedy ----------------
__global__ void __launch_bounds__(256) k_nms() {
    __shared__ uint32_t hist[1025];
    __shared__ uint32_t chkey[CHNK];
    __shared__ uint16_t chidx[CHNK];
    __shared__ alignas(16) uint32_t rows[CHNK * 32];   // 32KB (fallback reuses as u64 keys)
    __shared__ uint32_t sup_sh[32];
    __shared__ float    kept_s[KPC];
    __shared__ int      kept_i[KPC];
    __shared__ uint32_t wsum[8];
    __shared__ int      s_cnt, s_bhi, s_kc, s_done, s_fb;

    const int c    = blockIdx.x;
    const int b    = blockIdx.y;
    const int tid  = threadIdx.x;
    const int lane = tid & 31;
    const uint32_t BASE = 0x80F;             // dbits(1.0f) >> 19

    #pragma unroll
    for (int k = 0; k < 4; k++) hist[tid * 4 + k] = 0;
    if (tid < 32) sup_sh[tid] = 0;
    if (tid == 0) { hist[1024] = 0; s_kc = 0; s_done = 0; s_fb = 0; }

    uint32_t key[4], binv[4]; bool val[4];
    #pragma unroll
    for (int k = 0; k < 4; k++) {
        int i = tid + k * 256;
        float s = g_scoresT[(b * CC + c) * NN + i];    // coalesced
        val[k] = (s > STHR);
        key[k] = dbits(s);
        int raw = (int)(key[k] >> 19) - (int)BASE;
        binv[k] = (uint32_t)min(max(raw, 0), 1023);
    }
    __syncthreads();
    #pragma unroll
    for (int k = 0; k < 4; k++) if (val[k]) atomicAdd(&hist[binv[k]], 1u);
    __syncthreads();

    // exclusive scan of 1024 bins (4 bins/thread, 8 warps)
    {
        uint32_t h[4];
        #pragma unroll
        for (int k = 0; k < 4; k++) h[k] = hist[4 * tid + k];
        uint32_t s4 = h[0] + h[1] + h[2] + h[3];
        uint32_t inc = s4;
        #pragma unroll
        for (int o = 1; o < 32; o <<= 1) {
            uint32_t v = __shfl_up_sync(0xffffffffu, inc, o);
            if ((tid & 31) >= o) inc += v;
        }
        if ((tid & 31) == 31) wsum[tid >> 5] = inc;
        __syncthreads();
        if (tid < 8) {
            uint32_t v = wsum[tid], in2 = v;
            #pragma unroll
            for (int o = 1; o < 8; o <<= 1) {
                uint32_t x = __shfl_up_sync(0x000000ffu, in2, o);
                if (tid >= o) in2 += x;
            }
            wsum[tid] = in2 - v;
        }
        __syncthreads();
        uint32_t excl = wsum[tid >> 5] + (inc - s4);
        uint32_t c1 = excl + h[0], c2 = c1 + h[1], c3 = c2 + h[2], c4 = excl + s4;
        hist[4 * tid] = excl; hist[4 * tid + 1] = c1; hist[4 * tid + 2] = c2; hist[4 * tid + 3] = c3;
        if (tid == 255) hist[1024] = c4;
    }
    __syncthreads();

    const int total = (int)hist[1024];
    uint32_t sup = 0;
    int      kc  = 0;
    int binLo = 0;

    for (int chunk = 0; chunk < 8; chunk++) {
        if (s_kc >= KPC || s_done >= total) break;

        if (tid == 0) { s_bhi = binLo; s_cnt = 0; }
        __syncthreads();
        const uint32_t base = hist[binLo];
        #pragma unroll
        for (int k = 1; k <= 4; k++) {
            int e = 4 * tid + k;
            if (hist[e] - base <= (uint32_t)CHNK) atomicMax(&s_bhi, e);
        }
        __syncthreads();
        const int binHi = s_bhi;
        if (binHi == binLo) { if (tid == 0) s_fb = 1; __syncthreads(); break; }
        const int rangeCnt = (int)(hist[binHi] - base);

        // compact chunk members, dropping already-suppressed candidates (exact: monotone)
        #pragma unroll
        for (int k = 0; k < 4; k++) {
            int i = tid + k * 256;
            if (val[k] && binv[k] >= (uint32_t)binLo && binv[k] < (uint32_t)binHi &&
                !((sup_sh[i >> 5] >> (i & 31)) & 1u)) {
                int pos = atomicAdd(&s_cnt, 1);
                chkey[pos] = key[k];
                chidx[pos] = (uint16_t)i;
            }
        }
        __syncthreads();
        const int P = s_cnt;
        if (tid >= P) { chkey[tid] = 0xFFFFFFFFu; chidx[tid] = 0xFFFF; }
        __syncthreads();

        if (P > 0) {
            if (P <= 32) {
                if (tid < 32) {
                    uint32_t mk = chkey[tid], mi = chidx[tid];
                    for (int k2 = 2; k2 <= 32; k2 <<= 1) {
                        for (int j = k2 >> 1; j > 0; j >>= 1) {
                            uint32_t pk = __shfl_xor_sync(0xffffffffu, mk, j);
                            uint32_t pi = __shfl_xor_sync(0xffffffffu, mi, j);
                            bool up = ((tid & k2) == 0);
                            bool keep_min = (((tid & j) == 0) == up);
                            bool plt = (pk < mk) || (pk == mk && pi < mi);
                            if (keep_min == plt) { mk = pk; mi = pi; }
                        }
                    }
                    chkey[tid] = mk; chidx[tid] = (uint16_t)mi;
                }
                __syncthreads();
            } else {
                uint32_t mk = chkey[tid], mi = chidx[tid];
                for (int k2 = 2; k2 <= CHNK; k2 <<= 1) {
                    for (int j = k2 >> 1; j > 0; j >>= 1) {
                        if (j >= 32) {
                            __syncthreads();
                            chkey[tid] = mk; chidx[tid] = (uint16_t)mi;
                            __syncthreads();
                            int p2 = tid ^ j;
                            uint32_t pk = chkey[p2], pi = chidx[p2];
                            bool up = ((tid & k2) == 0);
                            bool keep_min = (((tid & j) == 0) == up);
                            bool plt = (pk < mk) || (pk == mk && pi < mi);
                            if (keep_min == plt) { mk = pk; mi = pi; }
                        } else {
                            uint32_t pk = __shfl_xor_sync(0xffffffffu, mk, j);
                            uint32_t pi = __shfl_xor_sync(0xffffffffu, mi, j);
                            bool up = ((tid & k2) == 0);
                            bool keep_min = (((tid & j) == 0) == up);
                            bool plt = (pk < mk) || (pk == mk && pi < mi);
                            if (keep_min == plt) { mk = pk; mi = pi; }
                        }
                    }
                }
                __syncthreads();
                chkey[tid] = mk; chidx[tid] = (uint16_t)mi;
                __syncthreads();
            }

            // preload chunk mask rows (vectorized, alive candidates only)
            {
                const uint4* gm4 = reinterpret_cast<const uint4*>(g_mask);
                uint4* rw4 = reinterpret_cast<uint4*>(rows);
                for (int l = tid; l < P * 8; l += 256) {
                    int r = l >> 3, q = l & 7;
                    int o = (int)chidx[r];
                    rw4[(r << 3) | q] = gm4[(b * NN + o) * 8 + q];
                }
            }
            __syncthreads();

            // group-of-32 parallel greedy on warp 0
            if (tid < 32) {
                const uint32_t lowmask = (lane == 0) ? 0u : (0xffffffffu >> (32 - lane));
                for (int g0 = 0; g0 < P && kc < KPC; g0 += 32) {
                    int l = g0 + lane;
                    bool has = (l < P);
                    uint32_t o = 0, keyv = 0xFFFFFFFFu;
                    if (has) { o = chidx[l]; keyv = chkey[l]; }
                    uint32_t wl2 = o >> 5, bl = o & 31;

                    uint32_t wsup = __shfl_sync(0xffffffffu, sup, (int)wl2);
                    bool alive0 = has && !((wsup >> bl) & 1u);
                    uint32_t alive_mask = __ballot_sync(0xffffffffu, alive0);
                    if (alive_mask == 0) continue;

                    uint32_t colbits = 0;
                    int gcnt = min(32, P - g0);
                    for (int m = 0; m < gcnt; m++) {
                        uint32_t rm = rows[((g0 + m) << 5) + wl2];
                        colbits |= ((rm >> bl) & 1u) << m;
                    }

                    #pragma unroll 4
                    for (int it = 0; it < 32; it++) {
                        bool a = alive0 && ((alive_mask & colbits & lowmask) == 0);
                        uint32_t nm = __ballot_sync(0xffffffffu, a);
                        if (nm == alive_mask) break;
                        alive_mask = nm;
                    }

                    int navail = KPC - kc;
                    int myrank = __popc(alive_mask & lowmask);
                    bool keepme = ((alive_mask >> lane) & 1u) && (myrank < navail);
                    uint32_t kept_mask = __ballot_sync(0xffffffffu, keepme);
                    if (keepme) {
                        kept_i[kc + myrank] = (int)o;
                        kept_s[kc + myrank] = undbits_pos(keyv);
                    }
                    uint32_t km = kept_mask;
                    while (km) {
                        int m = __ffs(km) - 1; km &= km - 1;
                        sup |= rows[((g0 + m) << 5) + lane];
                    }
                    kc += __popc(kept_mask);
                }
                sup_sh[lane] = sup;
                if (lane == 0) s_kc = kc;
            }
        }
        __syncthreads();
        if (tid == 0) s_done += rangeCnt;
        binLo = binHi;
        __syncthreads();
    }
    __syncthreads();

    // fallback: degenerate distribution (never expected) -> full sort + sequential greedy
    if (s_fb || (s_kc < KPC && s_done < total)) {
        uint64_t* keys = reinterpret_cast<uint64_t*>(rows);
        #pragma unroll
        for (int k = 0; k < 4; k++) {
            int i = tid + k * 256;
            uint32_t kb = val[k] ? key[k] : 0xFFFFFFFFu;
            keys[i] = (((uint64_t)kb) << 32) | (uint32_t)i;
        }
        __syncthreads();
        for (int k2 = 2; k2 <= NN; k2 <<= 1) {
            for (int j = k2 >> 1; j > 0; j >>= 1) {
                #pragma unroll
                for (int t2 = 0; t2 < 4; t2++) {
                    int i2 = tid + t2 * 256, ixj = i2 ^ j;
                    if (ixj > i2) {
                        uint64_t a = keys[i2], d2 = keys[ixj];
                        bool up = ((i2 & k2) == 0);
                        if ((a > d2) == up) { keys[i2] = d2; keys[ixj] = a; }
                    }
                }
                __syncthreads();
            }
        }
        if (tid < 32) {
            uint32_t sup2 = 0; int kc2 = 0;
            for (int p = 0; p < NN; p++) {
                uint64_t kk = keys[p];
                if ((uint32_t)(kk >> 32) == 0xFFFFFFFFu) break;
                uint32_t o   = (uint32_t)kk & (NN - 1);
                uint32_t row = g_mask[(b * NN + o) * 32 + tid];
                uint32_t wv  = __shfl_sync(0xffffffffu, sup2, (int)(o >> 5));
                if (!((wv >> (o & 31)) & 1u)) {
                    if (tid == 0) { kept_i[kc2] = (int)o; kept_s[kc2] = undbits_pos((uint32_t)(kk >> 32)); }
                    sup2 |= row;
                    kc2++;
                    if (kc2 == KPC) break;
                }
            }
            if (tid == 0) s_kc = kc2;
        }
        __syncthreads();
    }

    const int kcf = s_kc;
    if (tid < KPC) {
        int slot = (b * CC + c) * KPC + tid;
        if (tid < kcf) { g_stage_s[slot] = kept_s[tid]; g_stage_b[slot] = kept_i[tid]; }
        else           { g_stage_s[slot] = NEGV;        g_stage_b[slot] = 0; }
    }
}

// ---------------- K3: per-image top-300 of 8000 + output (proven R10 version) ----------------
__global__ void __launch_bounds__(1024) k_final(const float* __restrict__ boxes,
                                                float* __restrict__ out) {
    __shared__ uint32_t hist[4097];
    __shared__ uint32_t fkey[FSEL];
    __shared__ uint16_t fidx[FSEL];
    __shared__ uint32_t wsum[32];
    __shared__ int      s_cnt, s_bsel, s_total, s_m;

    const int b   = blockIdx.x;
    const int tid = threadIdx.x;
    const int M   = CC * KPC;
    const uint32_t BASE13 = 0x203FF;

    #pragma unroll
    for (int k = 0; k < 4; k++) hist[tid * 4 + k] = 0;
    if (tid == 0) { hist[4096] = 0; s_cnt = 0; s_bsel = 0; }

    float vals[8]; int idxs[8]; uint32_t keyb[8]; uint32_t binb[8]; bool valb[8];
    #pragma unroll
    for (int k = 0; k < 8; k++) {
        int f = tid + k * 1024;
        float s = (f < M) ? g_stage_s[b * M + f] : NEGV;
        vals[k] = s; idxs[k] = (f < M) ? f : 0;
        valb[k] = (s > NEGV * 0.5f);
        keyb[k] = dbits(s);
        int raw = (int)(keyb[k] >> 13) - (int)BASE13;
        binb[k] = (uint32_t)min(max(raw, 0), 4095);
    }
    __syncthreads();
    #pragma unroll
    for (int k = 0; k < 8; k++) if (valb[k]) atomicAdd(&hist[binb[k]], 1u);
    __syncthreads();

    uint32_t h[4];
    #pragma unroll
    for (int k = 0; k < 4; k++) h[k] = hist[4 * tid + k];
    uint32_t s4 = h[0] + h[1] + h[2] + h[3];
    uint32_t inc = s4;
    #pragma unroll
    for (int o = 1; o < 32; o <<= 1) {
        uint32_t v = __shfl_up_sync(0xffffffffu, inc, o);
        if ((tid & 31) >= o) inc += v;
    }
    if ((tid & 31) == 31) wsum[tid >> 5] = inc;
    __syncthreads();
    if (tid < 32) {
        uint32_t v = wsum[tid], in2 = v;
        #pragma unroll
        for (int o = 1; o < 32; o <<= 1) {
            uint32_t x = __shfl_up_sync(0xffffffffu, in2, o);
            if (tid >= o) in2 += x;
        }
        wsum[tid] = in2 - v;
    }
    __syncthreads();
    uint32_t excl = wsum[tid >> 5] + (inc - s4);
    uint32_t cum1 = excl + h[0], cum2 = cum1 + h[1], cum3 = cum2 + h[2], cum4 = excl + s4;
    hist[4 * tid] = excl; hist[4 * tid + 1] = cum1; hist[4 * tid + 2] = cum2; hist[4 * tid + 3] = cum3;
    if (tid == 1023) hist[4096] = cum4;
    if (cum1 <= (uint32_t)FSEL) atomicMax(&s_bsel, 4 * tid + 1);
    if (cum2 <= (uint32_t)FSEL) atomicMax(&s_bsel, 4 * tid + 2);
    if (cum3 <= (uint32_t)FSEL) atomicMax(&s_bsel, 4 * tid + 3);
    if (cum4 <= (uint32_t)FSEL) atomicMax(&s_bsel, 4 * tid + 4);
    __syncthreads();

    const int Bsel  = s_bsel;
    int P           = (int)hist[Bsel];
    const int total = (int)hist[4096];

    if (P >= MAXT || P >= total) {
        #pragma unroll
        for (int k = 0; k < 8; k++) {
            if (valb[k] && binb[k] < (uint32_t)Bsel) {
                int pos = atomicAdd(&s_cnt, 1);
                if (pos < FSEL) { fkey[pos] = keyb[k]; fidx[pos] = (uint16_t)idxs[k]; }
            }
        }
        if (tid == 0) s_m = P;
    } else {
        float lo = 0.0f, hi2 = 1.0f;
        for (int it = 0; it < 30; it++) {
            float mid = 0.5f * (lo + hi2);
            int cnt = 0;
            #pragma unroll
            for (int k = 0; k < 8; k++) cnt += (vals[k] > mid);
            #pragma unroll
            for (int o = 16; o; o >>= 1) cnt += __shfl_down_sync(0xffffffffu, cnt, o);
            if ((tid & 31) == 0) wsum[tid >> 5] = (uint32_t)cnt;
            __syncthreads();
            if (tid == 0) {
                int tot = 0;
                #pragma unroll
                for (int w2 = 0; w2 < 32; w2++) tot += (int)wsum[w2];
                s_total = tot;
            }
            __syncthreads();
            if (s_total >= MAXT) lo = mid; else hi2 = mid;
            __syncthreads();
        }
        if (tid == 0) s_cnt = 0;
        __syncthreads();
        #pragma unroll
        for (int k = 0; k < 8; k++) {
            if (vals[k] > lo) {
                int pos = atomicAdd(&s_cnt, 1);
                if (pos < FSEL) { fkey[pos] = dbits(vals[k]); fidx[pos] = (uint16_t)idxs[k]; }
            }
        }
        __syncthreads();
        if (tid == 0) s_m = min(s_cnt, FSEL);
    }
    __syncthreads();
    const int m = s_m;
    if (tid < FSEL && tid >= m) { fkey[tid] = 0xFFFFFFFFu; fidx[tid] = 0xFFFF; }
    __syncthreads();

    {
        uint32_t mk = 0xFFFFFFFFu, mi = 0xFFFFu;
        if (tid < FSEL) { mk = fkey[tid]; mi = fidx[tid]; }
        for (int k2 = 2; k2 <= FSEL; k2 <<= 1) {
            for (int j = k2 >> 1; j > 0; j >>= 1) {
                if (j >= 32) {
                    __syncthreads();
                    if (tid < FSEL) { fkey[tid] = mk; fidx[tid] = (uint16_t)mi; }
                    __syncthreads();
                    if (tid < FSEL) {
                        int p2 = tid ^ j;
                        uint32_t pk = fkey[p2], pi = fidx[p2];
                        bool up = ((tid & k2) == 0);
                        bool keep_min = (((tid & j) == 0) == up);
                        bool plt = (pk < mk) || (pk == mk && pi < mi);
                        if (keep_min == plt) { mk = pk; mi = pi; }
                    }
                } else if (tid < FSEL) {
                    uint32_t pk = __shfl_xor_sync(0xffffffffu, mk, j);
                    uint32_t pi = __shfl_xor_sync(0xffffffffu, mi, j);
                    bool up = ((tid & k2) == 0);
                    bool keep_min = (((tid & j) == 0) == up);
                    bool plt = (pk < mk) || (pk == mk && pi < mi);
                    if (keep_min == plt) { mk = pk; mi = pi; }
                }
            }
        }
        __syncthreads();
        if (tid < FSEL) { fkey[tid] = mk; fidx[tid] = (uint16_t)mi; }
        __syncthreads();
    }

    if (tid < MAXT) {
        bool valid = (tid < m);
        float sc = 0.0f, cls = 0.0f, bx0 = 0.0f, bx1 = 0.0f, bx2 = 0.0f, bx3 = 0.0f;
        if (valid) {
            int f = (int)fidx[tid];
            sc  = g_stage_s[b * M + f];
            cls = (float)(f / KPC);
            int bidx = g_stage_b[b * M + f];
            float4 bv = reinterpret_cast<const float4*>(boxes)[b * NN + bidx];
            bx0 = fminf(fmaxf(bv.x, 0.0f), 1.0f);
            bx1 = fminf(fmaxf(bv.y, 0.0f), 1.0f);
            bx2 = fminf(fmaxf(bv.z, 0.0f), 1.0f);
            bx3 = fminf(fmaxf(bv.w, 0.0f), 1.0f);
        }
        out[b * MAXT + tid] = sc;
        float* ob = out + BB * MAXT + (b * MAXT + tid) * 4;
        ob[0] = bx0; ob[1] = bx1; ob[2] = bx2; ob[3] = bx3;
        out[BB * MAXT * 5 + b * MAXT + tid] = cls;
    }
    if (tid == 0) out[BB * MAXT * 6 + b] = (float)min(m, MAXT);
}

// ---------------- launch ----------------
extern "C" void kernel_launch(void* const* d_in, const int* in_sizes, int n_in,
                              void* d_out, int out_size) {
    const float* scores = (const float*)d_in[0];   // [4,1024,80] f32
    const float* boxes  = (const float*)d_in[1];   // [4,1024,1,4] f32
    float* out = (float*)d_out;

    k_tr<<<dim3(32, BB), 256>>>(scores);
    k_mask<<<dim3(256, BB), 128>>>((const float4*)boxes);
    k_nms<<<dim3(CC, BB), 256>>>();
    k_final<<<BB, 1024>>>(boxes, out);
}

// round 16
// speedup vs baseline: 1.2551x; 1.0703x over previous
#include <cuda_runtime.h>
#include <stdint.h>

#define BB   4
#define NN   1024
#define CC   80
#define KPC  100
#define MAXT 300
#define NEGV (-1e30f)
#define STHR 0.001f
#define CHNK 256     // k_nms chunk capacity
#define FSEL 512     // k_final selection cap

// ---------------- scratch ----------------
__device__ uint32_t g_mask[BB * NN * 32];
__device__ float    g_stage_s[BB * CC * KPC];
__device__ int      g_stage_b[BB * CC * KPC];

__device__ __forceinline__ uint32_t dbits(float f) {
    uint32_t u = __float_as_uint(f);
    return (u & 0x80000000u) ? u : (u ^ 0x7fffffffu);
}
__device__ __forceinline__ float undbits_pos(uint32_t d) {
    return __uint_as_float(d ^ 0x7fffffffu);   // valid for positive originals
}

// ---------------- K1: pairwise IoU>0.5 bitmask (2 rows/thread, 16-bit stores) ----------------
__global__ void __launch_bounds__(128) k_mask(const float4* __restrict__ boxes) {
    __shared__ float4 sj[256]; __shared__ float aj[256];
    __shared__ float4 si[16];  __shared__ float ai[16];
    const int b  = blockIdx.y;
    const int rt = blockIdx.x >> 2;
    const int ct = blockIdx.x & 3;
    const int tid = threadIdx.x;

    #pragma unroll
    for (int k = 0; k < 2; k++) {
        int i = tid + k * 128;
        float4 v = boxes[b * NN + ct * 256 + i];
        float y1 = fminf(v.x, v.z), y2 = fmaxf(v.x, v.z);
        float x1 = fminf(v.y, v.w), x2 = fmaxf(v.y, v.w);
        sj[i] = make_float4(y1, x1, y2, x2);
        aj[i] = (y2 - y1) * (x2 - x1);
    }
    if (tid < 16) {
        float4 v = boxes[b * NN + rt * 16 + tid];
        float y1 = fminf(v.x, v.z), y2 = fmaxf(v.x, v.z);
        float x1 = fminf(v.y, v.w), x2 = fmaxf(v.y, v.w);
        si[tid] = make_float4(y1, x1, y2, x2);
        ai[tid] = (y2 - y1) * (x2 - x1);
    }
    __syncthreads();

    const int r    = tid >> 4;
    const int hw   = tid & 15;
    const int lane = tid & 31;
    float4 A0 = si[r],     A1 = si[r + 8];
    float  a0 = ai[r],     a1 = ai[r + 8];
    uint32_t bits0 = 0, bits1 = 0;

    #pragma unroll
    for (int t = 0; t < 16; t++) {
        int c  = (t + lane) & 15;
        int jl = hw * 16 + c;
        float4 Bx = sj[jl];
        float  ab = aj[jl];
        {
            float ih    = fmaxf(fminf(A0.z, Bx.z) - fmaxf(A0.x, Bx.x), 0.0f);
            float iw2   = fmaxf(fminf(A0.w, Bx.w) - fmaxf(A0.y, Bx.y), 0.0f);
            float inter = ih * iw2;
            float uni   = fmaxf(a0 + ab - inter, 1e-12f);
            if ((inter + inter) - uni > uni * 0x1p-24f) bits0 |= (1u << c);
        }
        {
            float ih    = fmaxf(fminf(A1.z, Bx.z) - fmaxf(A1.x, Bx.x), 0.0f);
            float iw2   = fmaxf(fminf(A1.w, Bx.w) - fmaxf(A1.y, Bx.y), 0.0f);
            float inter = ih * iw2;
            float uni   = fmaxf(a1 + ab - inter, 1e-12f);
            if ((inter + inter) - uni > uni * 0x1p-24f) bits1 |= (1u << c);
        }
    }
    uint16_t* gm16 = reinterpret_cast<uint16_t*>(g_mask);
    gm16[(size_t)(b * NN + rt * 16 + r)     * 64 + ct * 16 + hw] = (uint16_t)bits0;
    gm16[(size_t)(b * NN + rt * 16 + r + 8) * 64 + ct * 16 + hw] = (uint16_t)bits1;
}

// ---------------- K2: chunked bucket-select + alive filter + tiered sort + ballot greedy ----------------
__global__ void __launch_bounds__(256) k_nms(const float* __restrict__ scores) {
    __shared__ uint32_t hist[1025];
    __shared__ uint32_t chkey[CHNK];
    __shared__ uint16_t chidx[CHNK];
    __shared__ alignas(16) uint32_t rows[CHNK * 32];
    __shared__ uint32_t sup_sh[32];
    __shared__ float    kept_s[KPC];
    __shared__ int      kept_i[KPC];
    __shared__ uint32_t wsum[8];
    __shared__ int      s_cnt, s_bhi, s_kc, s_done, s_fb;

    const int c    = blockIdx.x;
    const int b    = blockIdx.y;
    const int tid  = threadIdx.x;
    const int lane = tid & 31;
    const uint32_t BASE = 0x80F;

    #pragma unroll
    for (int k = 0; k < 4; k++) hist[tid * 4 + k] = 0;
    if (tid < 32) sup_sh[tid] = 0;
    if (tid == 0) { hist[1024] = 0; s_kc = 0; s_done = 0; s_fb = 0; }

    uint32_t key[4], binv[4]; bool val[4];
    #pragma unroll
    for (int k = 0; k < 4; k++) {
        int i = tid + k * 256;
        float s = scores[(b * NN + i) * CC + c];
        val[k] = (s > STHR);
        key[k] = dbits(s);
        int raw = (int)(key[k] >> 19) - (int)BASE;
        binv[k] = (uint32_t)min(max(raw, 0), 1023);
    }
    __syncthreads();
    #pragma unroll
    for (int k = 0; k < 4; k++) if (val[k]) atomicAdd(&hist[binv[k]], 1u);
    __syncthreads();

    // exclusive scan of 1024 bins (4 bins/thread, 8 warps)
    {
        uint32_t h[4];
        #pragma unroll
        for (int k = 0; k < 4; k++) h[k] = hist[4 * tid + k];
        uint32_t s4 = h[0] + h[1] + h[2] + h[3];
        uint32_t inc = s4;
        #pragma unroll
        for (int o = 1; o < 32; o <<= 1) {
            uint32_t v = __shfl_up_sync(0xffffffffu, inc, o);
            if ((tid & 31) >= o) inc += v;
        }
        if ((tid & 31) == 31) wsum[tid >> 5] = inc;
        __syncthreads();
        if (tid < 8) {
            uint32_t v = wsum[tid], in2 = v;
            #pragma unroll
            for (int o = 1; o < 8; o <<= 1) {
                uint32_t x = __shfl_up_sync(0x000000ffu, in2, o);
                if (tid >= o) in2 += x;
            }
            wsum[tid] = in2 - v;
        }
        __syncthreads();
        uint32_t excl = wsum[tid >> 5] + (inc - s4);
        uint32_t c1 = excl + h[0], c2 = c1 + h[1], c3 = c2 + h[2], c4 = excl + s4;
        hist[4 * tid] = excl; hist[4 * tid + 1] = c1; hist[4 * tid + 2] = c2; hist[4 * tid + 3] = c3;
        if (tid == 255) hist[1024] = c4;
    }
    __syncthreads();

    const int total = (int)hist[1024];
    uint32_t sup = 0;
    int      kc  = 0;
    int binLo = 0;

    for (int chunk = 0; chunk < 8; chunk++) {
        if (s_kc >= KPC || s_done >= total) break;

        if (tid == 0) { s_bhi = binLo; s_cnt = 0; }
        __syncthreads();
        const uint32_t base = hist[binLo];
        #pragma unroll
        for (int k = 1; k <= 4; k++) {
            int e = 4 * tid + k;
            if (hist[e] - base <= (uint32_t)CHNK) atomicMax(&s_bhi, e);
        }
        __syncthreads();
        const int binHi = s_bhi;
        if (binHi == binLo) { if (tid == 0) s_fb = 1; __syncthreads(); break; }
        const int rangeCnt = (int)(hist[binHi] - base);

        #pragma unroll
        for (int k = 0; k < 4; k++) {
            int i = tid + k * 256;
            if (val[k] && binv[k] >= (uint32_t)binLo && binv[k] < (uint32_t)binHi &&
                !((sup_sh[i >> 5] >> (i & 31)) & 1u)) {
                int pos = atomicAdd(&s_cnt, 1);
                chkey[pos] = key[k];
                chidx[pos] = (uint16_t)i;
            }
        }
        __syncthreads();
        const int P = s_cnt;
        if (tid >= P) { chkey[tid] = 0xFFFFFFFFu; chidx[tid] = 0xFFFF; }
        __syncthreads();

        if (P > 0) {
            if (P <= 32) {
                if (tid < 32) {
                    uint32_t mk = chkey[tid], mi = chidx[tid];
                    for (int k2 = 2; k2 <= 32; k2 <<= 1) {
                        for (int j = k2 >> 1; j > 0; j >>= 1) {
                            uint32_t pk = __shfl_xor_sync(0xffffffffu, mk, j);
                            uint32_t pi = __shfl_xor_sync(0xffffffffu, mi, j);
                            bool up = ((tid & k2) == 0);
                            bool keep_min = (((tid & j) == 0) == up);
                            bool plt = (pk < mk) || (pk == mk && pi < mi);
                            if (keep_min == plt) { mk = pk; mi = pi; }
                        }
                    }
                    chkey[tid] = mk; chidx[tid] = (uint16_t)mi;
                }
                __syncthreads();
            } else {
                uint32_t mk = chkey[tid], mi = chidx[tid];
                for (int k2 = 2; k2 <= CHNK; k2 <<= 1) {
                    for (int j = k2 >> 1; j > 0; j >>= 1) {
                        if (j >= 32) {
                            __syncthreads();
                            chkey[tid] = mk; chidx[tid] = (uint16_t)mi;
                            __syncthreads();
                            int p2 = tid ^ j;
                            uint32_t pk = chkey[p2], pi = chidx[p2];
                            bool up = ((tid & k2) == 0);
                            bool keep_min = (((tid & j) == 0) == up);
                            bool plt = (pk < mk) || (pk == mk && pi < mi);
                            if (keep_min == plt) { mk = pk; mi = pi; }
                        } else {
                            uint32_t pk = __shfl_xor_sync(0xffffffffu, mk, j);
                            uint32_t pi = __shfl_xor_sync(0xffffffffu, mi, j);
                            bool up = ((tid & k2) == 0);
                            bool keep_min = (((tid & j) == 0) == up);
                            bool plt = (pk < mk) || (pk == mk && pi < mi);
                            if (keep_min == plt) { mk = pk; mi = pi; }
                        }
                    }
                }
                __syncthreads();
                chkey[tid] = mk; chidx[tid] = (uint16_t)mi;
                __syncthreads();
            }

            {
                const uint4* gm4 = reinterpret_cast<const uint4*>(g_mask);
                uint4* rw4 = reinterpret_cast<uint4*>(rows);
                for (int l = tid; l < P * 8; l += 256) {
                    int r = l >> 3, q = l & 7;
                    int o = (int)chidx[r];
                    rw4[(r << 3) | q] = gm4[(b * NN + o) * 8 + q];
                }
            }
            __syncthreads();

            if (tid < 32) {
                const uint32_t lowmask = (lane == 0) ? 0u : (0xffffffffu >> (32 - lane));
                for (int g0 = 0; g0 < P && kc < KPC; g0 += 32) {
                    int l = g0 + lane;
                    bool has = (l < P);
                    uint32_t o = 0, keyv = 0xFFFFFFFFu;
                    if (has) { o = chidx[l]; keyv = chkey[l]; }
                    uint32_t wl2 = o >> 5, bl = o & 31;

                    uint32_t wsup = __shfl_sync(0xffffffffu, sup, (int)wl2);
                    bool alive0 = has && !((wsup >> bl) & 1u);
                    uint32_t alive_mask = __ballot_sync(0xffffffffu, alive0);
                    if (alive_mask == 0) continue;

                    uint32_t colbits = 0;
                    int gcnt = min(32, P - g0);
                    for (int m = 0; m < gcnt; m++) {
                        uint32_t rm = rows[((g0 + m) << 5) + wl2];
                        colbits |= ((rm >> bl) & 1u) << m;
                    }

                    #pragma unroll 4
                    for (int it = 0; it < 32; it++) {
                        bool a = alive0 && ((alive_mask & colbits & lowmask) == 0);
                        uint32_t nm = __ballot_sync(0xffffffffu, a);
                        if (nm == alive_mask) break;
                        alive_mask = nm;
                    }

                    int navail = KPC - kc;
                    int myrank = __popc(alive_mask & lowmask);
                    bool keepme = ((alive_mask >> lane) & 1u) && (myrank < navail);
                    uint32_t kept_mask = __ballot_sync(0xffffffffu, keepme);
                    if (keepme) {
                        kept_i[kc + myrank] = (int)o;
                        kept_s[kc + myrank] = undbits_pos(keyv);
                    }
                    uint32_t km = kept_mask;
                    while (km) {
                        int m = __ffs(km) - 1; km &= km - 1;
                        sup |= rows[((g0 + m) << 5) + lane];
                    }
                    kc += __popc(kept_mask);
                }
                sup_sh[lane] = sup;
                if (lane == 0) s_kc = kc;
            }
        }
        __syncthreads();
        if (tid == 0) s_done += rangeCnt;
        binLo = binHi;
        __syncthreads();
    }
    __syncthreads();

    if (s_fb || (s_kc < KPC && s_done < total)) {
        uint64_t* keys = reinterpret_cast<uint64_t*>(rows);
        #pragma unroll
        for (int k = 0; k < 4; k++) {
            int i = tid + k * 256;
            uint32_t kb = val[k] ? key[k] : 0xFFFFFFFFu;
            keys[i] = (((uint64_t)kb) << 32) | (uint32_t)i;
        }
        __syncthreads();
        for (int k2 = 2; k2 <= NN; k2 <<= 1) {
            for (int j = k2 >> 1; j > 0; j >>= 1) {
                #pragma unroll
                for (int t2 = 0; t2 < 4; t2++) {
                    int i2 = tid + t2 * 256, ixj = i2 ^ j;
                    if (ixj > i2) {
                        uint64_t a = keys[i2], d2 = keys[ixj];
                        bool up = ((i2 & k2) == 0);
                        if ((a > d2) == up) { keys[i2] = d2; keys[ixj] = a; }
                    }
                }
                __syncthreads();
            }
        }
        if (tid < 32) {
            uint32_t sup2 = 0; int kc2 = 0;
            for (int p = 0; p < NN; p++) {
                uint64_t kk = keys[p];
                if ((uint32_t)(kk >> 32) == 0xFFFFFFFFu) break;
                uint32_t o   = (uint32_t)kk & (NN - 1);
                uint32_t row = g_mask[(b * NN + o) * 32 + tid];
                uint32_t wv  = __shfl_sync(0xffffffffu, sup2, (int)(o >> 5));
                if (!((wv >> (o & 31)) & 1u)) {
                    if (tid == 0) { kept_i[kc2] = (int)o; kept_s[kc2] = undbits_pos((uint32_t)(kk >> 32)); }
                    sup2 |= row;
                    kc2++;
                    if (kc2 == KPC) break;
                }
            }
            if (tid == 0) s_kc = kc2;
        }
        __syncthreads();
    }

    const int kcf = s_kc;
    if (tid < KPC) {
        int slot = (b * CC + c) * KPC + tid;
        if (tid < kcf) { g_stage_s[slot] = kept_s[tid]; g_stage_b[slot] = kept_i[tid]; }
        else           { g_stage_s[slot] = NEGV;        g_stage_b[slot] = 0; }
    }
}

// ---------------- K3: per-image top-300 of 8000 (slim, 512 threads) ----------------
__global__ void __launch_bounds__(512) k_final(const float* __restrict__ boxes,
                                               float* __restrict__ out) {
    __shared__ uint32_t hist[4097];
    __shared__ uint32_t fkey[FSEL];
    __shared__ uint16_t fidx[FSEL];
    __shared__ uint32_t wsum[16];
    __shared__ int      s_cnt, s_bsel, s_total, s_m;

    const int b   = blockIdx.x;
    const int tid = threadIdx.x;
    const int M   = CC * KPC;                 // 8000
    const uint32_t BASE13 = 0x203FF;          // dbits(1.0f) >> 13

    #pragma unroll
    for (int k = 0; k < 8; k++) hist[tid * 8 + k] = 0;
    if (tid == 0) { hist[4096] = 0; s_cnt = 0; s_bsel = 0; }
    __syncthreads();

    // phase 1: histogram only (nothing kept live)
    #pragma unroll
    for (int k = 0; k < 16; k++) {
        int f = tid + k * 512;
        if (f < M) {
            float s = g_stage_s[b * M + f];
            if (s > NEGV * 0.5f) {
                uint32_t kb = dbits(s);
                int raw = (int)(kb >> 13) - (int)BASE13;
                uint32_t bin = (uint32_t)min(max(raw, 0), 4095);
                atomicAdd(&hist[bin], 1u);
            }
        }
    }
    __syncthreads();

    // exclusive scan of 4096 bins (8 bins/thread, 16 warps)
    {
        uint32_t h[8];
        #pragma unroll
        for (int k = 0; k < 8; k++) h[k] = hist[8 * tid + k];
        uint32_t s8 = 0;
        #pragma unroll
        for (int k = 0; k < 8; k++) s8 += h[k];
        uint32_t inc = s8;
        #pragma unroll
        for (int o = 1; o < 32; o <<= 1) {
            uint32_t v = __shfl_up_sync(0xffffffffu, inc, o);
            if ((tid & 31) >= o) inc += v;
        }
        if ((tid & 31) == 31) wsum[tid >> 5] = inc;
        __syncthreads();
        if (tid < 16) {
            uint32_t v = wsum[tid], in2 = v;
            #pragma unroll
            for (int o = 1; o < 16; o <<= 1) {
                uint32_t x = __shfl_up_sync(0x0000ffffu, in2, o);
                if (tid >= o) in2 += x;
            }
            wsum[tid] = in2 - v;
        }
        __syncthreads();
        uint32_t cum = wsum[tid >> 5] + (inc - s8);   // exclusive at bin 8*tid
        #pragma unroll
        for (int k = 0; k < 8; k++) {
            hist[8 * tid + k] = cum;
            cum += h[k];
            // boundary e = 8*tid+k+1 has cumulative = cum
            if (cum <= (uint32_t)FSEL) atomicMax(&s_bsel, 8 * tid + k + 1);
        }
        if (tid == 511) hist[4096] = cum;
    }
    __syncthreads();

    const int Bsel  = s_bsel;
    const int P     = (int)hist[Bsel];
    const int total = (int)hist[4096];

    if (P >= MAXT || P >= total) {
        // phase 2: reload + compact (L2-hot)
        #pragma unroll
        for (int k = 0; k < 16; k++) {
            int f = tid + k * 512;
            if (f < M) {
                float s = g_stage_s[b * M + f];
                if (s > NEGV * 0.5f) {
                    uint32_t kb = dbits(s);
                    int raw = (int)(kb >> 13) - (int)BASE13;
                    uint32_t bin = (uint32_t)min(max(raw, 0), 4095);
                    if (bin < (uint32_t)Bsel) {
                        int pos = atomicAdd(&s_cnt, 1);
                        if (pos < FSEL) { fkey[pos] = kb; fidx[pos] = (uint16_t)f; }
                    }
                }
            }
        }
        if (tid == 0) s_m = P;
    } else {
        // bisection fallback (correct for any distribution)
        float lo = 0.0f, hi2 = 1.0f;
        for (int it = 0; it < 30; it++) {
            float mid = 0.5f * (lo + hi2);
            int cnt = 0;
            #pragma unroll
            for (int k = 0; k < 16; k++) {
                int f = tid + k * 512;
                if (f < M) cnt += (g_stage_s[b * M + f] > mid);
            }
            #pragma unroll
            for (int o = 16; o; o >>= 1) cnt += __shfl_down_sync(0xffffffffu, cnt, o);
            if ((tid & 31) == 0) wsum[tid >> 5] = (uint32_t)cnt;
            __syncthreads();
            if (tid == 0) {
                int tot = 0;
                #pragma unroll
                for (int w2 = 0; w2 < 16; w2++) tot += (int)wsum[w2];
                s_total = tot;
            }
            __syncthreads();
            if (s_total >= MAXT) lo = mid; else hi2 = mid;
            __syncthreads();
        }
        if (tid == 0) s_cnt = 0;
        __syncthreads();
        #pragma unroll
        for (int k = 0; k < 16; k++) {
            int f = tid + k * 512;
            if (f < M) {
                float s = g_stage_s[b * M + f];
                if (s > lo) {
                    int pos = atomicAdd(&s_cnt, 1);
                    if (pos < FSEL) { fkey[pos] = dbits(s); fidx[pos] = (uint16_t)f; }
                }
            }
        }
        __syncthreads();
        if (tid == 0) s_m = min(s_cnt, FSEL);
    }
    __syncthreads();
    const int m = s_m;
    if (tid >= m) { fkey[tid] = 0xFFFFFFFFu; fidx[tid] = 0xFFFF; }
    __syncthreads();

    // hybrid bitonic sort 512 keys with 512 threads (1 elem/thread)
    {
        uint32_t mk = fkey[tid], mi = fidx[tid];
        for (int k2 = 2; k2 <= FSEL; k2 <<= 1) {
            for (int j = k2 >> 1; j > 0; j >>= 1) {
                if (j >= 32) {
                    __syncthreads();
                    fkey[tid] = mk; fidx[tid] = (uint16_t)mi;
                    __syncthreads();
                    int p2 = tid ^ j;
                    uint32_t pk = fkey[p2], pi = fidx[p2];
                    bool up = ((tid & k2) == 0);
                    bool keep_min = (((tid & j) == 0) == up);
                    bool plt = (pk < mk) || (pk == mk && pi < mi);
                    if (keep_min == plt) { mk = pk; mi = pi; }
                } else {
                    uint32_t pk = __shfl_xor_sync(0xffffffffu, mk, j);
                    uint32_t pi = __shfl_xor_sync(0xffffffffu, mi, j);
                    bool up = ((tid & k2) == 0);
                    bool keep_min = (((tid & j) == 0) == up);
                    bool plt = (pk < mk) || (pk == mk && pi < mi);
                    if (keep_min == plt) { mk = pk; mi = pi; }
                }
            }
        }
        __syncthreads();
        fkey[tid] = mk; fidx[tid] = (uint16_t)mi;
        __syncthreads();
    }

    if (tid < MAXT) {
        bool valid = (tid < m);
        float sc = 0.0f, cls = 0.0f, bx0 = 0.0f, bx1 = 0.0f, bx2 = 0.0f, bx3 = 0.0f;
        if (valid) {
            int f = (int)fidx[tid];
            sc  = g_stage_s[b * M + f];
            cls = (float)(f / KPC);
            int bidx = g_stage_b[b * M + f];
            float4 bv = reinterpret_cast<const float4*>(boxes)[b * NN + bidx];
            bx0 = fminf(fmaxf(bv.x, 0.0f), 1.0f);
            bx1 = fminf(fmaxf(bv.y, 0.0f), 1.0f);
            bx2 = fminf(fmaxf(bv.z, 0.0f), 1.0f);
            bx3 = fminf(fmaxf(bv.w, 0.0f), 1.0f);
        }
        out[b * MAXT + tid] = sc;
        float* ob = out + BB * MAXT + (b * MAXT + tid) * 4;
        ob[0] = bx0; ob[1] = bx1; ob[2] = bx2; ob[3] = bx3;
        out[BB * MAXT * 5 + b * MAXT + tid] = cls;
    }
    if (tid == 0) out[BB * MAXT * 6 + b] = (float)min(m, MAXT);
}

// ---------------- launch ----------------
extern "C" void kernel_launch(void* const* d_in, const int* in_sizes, int n_in,
                              void* d_out, int out_size) {
    const float* scores = (const float*)d_in[0];   // [4,1024,80] f32
    const float* boxes  = (const float*)d_in[1];   // [4,1024,1,4] f32
    float* out = (float*)d_out;

    k_mask<<<dim3(256, BB), 128>>>((const float4*)boxes);
    k_nms<<<dim3(CC, BB), 256>>>(scores);
    k_final<<<BB, 512>>>(boxes, out);
}